// round 16
// baseline (speedup 1.0000x reference)
#include <cuda_runtime.h>
#include <cuda_fp16.h>
#include <cstdint>

namespace {

typedef unsigned int u32;

constexpr int AST = 44;                    // A smem row stride (words; 80 fp16 + pad)
constexpr int BST = 44;                    // B smem row stride (words)
constexpr int A_WORDS = 64 * AST;          // 2816 per buffer (x2)
constexpr int B_WORDS = 256 * BST;         // 11264 (single buffer)
constexpr int XH_WORDS = 3072;             // per buffer: 4 pairs x 3 rows x 256 half2
constexpr int SMEM_TOTAL = (2 * A_WORDS + B_WORDS + 2 * XH_WORDS) * 4;  // 92160 B

// Packed fp16 weights: row oc (64), 320 words = 640 fp16 k-cols.
// k-order within iter (8 ch): word slot = ((ii&3)*2 + (ii>>2)) + 8*j, j=0..4
// (tap pair j of channel ii; taps 0..8 conv, 9 = quad M). B uses the same order.
__device__ u32 g_A[64 * 320];
__device__ float g_bias[64];

__device__ __forceinline__ void mma_f16(float* d, const u32* a, u32 b0, u32 b1) {
    asm volatile(
        "mma.sync.aligned.m16n8k16.row.col.f32.f16.f16.f32 "
        "{%0,%1,%2,%3}, {%4,%5,%6,%7}, {%8,%9}, {%0,%1,%2,%3};"
        : "+f"(d[0]), "+f"(d[1]), "+f"(d[2]), "+f"(d[3])
        : "r"(a[0]), "r"(a[1]), "r"(a[2]), "r"(a[3]), "r"(b0), "r"(b1));
}

__device__ __forceinline__ void ldmx4(u32* r, u32 addr) {
    asm volatile("ldmatrix.sync.aligned.m8n8.x4.shared.b16 {%0,%1,%2,%3}, [%4];"
                 : "=r"(r[0]), "=r"(r[1]), "=r"(r[2]), "=r"(r[3]) : "r"(addr));
}

__device__ __forceinline__ u32 smem_u32(const void* p) {
    u32 a;
    asm("{ .reg .u64 t; cvta.to.shared.u64 t, %1; cvt.u32.u64 %0, t; }" : "=r"(a) : "l"(p));
    return a;
}

__device__ __forceinline__ void cp_async16(u32 dst, const void* src) {
    asm volatile("cp.async.cg.shared.global [%0], [%1], 16;"
                 :: "r"(dst), "l"(src) : "memory");
}

// pack two f32 -> fp16x2 word (lo half = a, hi half = b)
__device__ __forceinline__ u32 h2pack(float a, float b) {
    u32 d;
    asm("cvt.rn.f16x2.f32 %0, %1, %2;" : "=r"(d) : "f"(b), "f"(a));
    return d;
}
__device__ __forceinline__ u32 prmt(u32 a, u32 b, u32 s) {
    u32 d;
    asm("prmt.b32 %0, %1, %2, %3;" : "=r"(d) : "r"(a), "r"(b), "r"(s));
    return d;
}
__device__ __forceinline__ u32 hmul2(u32 a, u32 b) {
    u32 d;
    asm("mul.rn.f16x2 %0, %1, %2;" : "=r"(d) : "r"(a), "r"(b));
    return d;
}

// grid 64 (channel i) x 256 threads (64 oc x 4 q-slices)
__global__ void precompute_kernel(const float* __restrict__ lw,
                                  const float* __restrict__ lb,
                                  const float* __restrict__ w2aw,
                                  const float* __restrict__ w2ab,
                                  const float* __restrict__ w2bw,
                                  const float* __restrict__ w2bb) {
    const int i = blockIdx.x;
    const int o = (int)threadIdx.x & 63;
    const int qq = (int)threadIdx.x >> 6;
    __shared__ float red[4][64];

    {
        const float* wb = w2bw + qq * 4096 + o * 64;
        const float* wa = w2aw + qq * 4096 + i;
        float m = 0.f;
#pragma unroll 8
        for (int mm = 0; mm < 64; mm++) m = fmaf(wb[mm], wa[mm * 64], m);
        red[qq][o] = m;
    }
    __syncthreads();

    if (qq == 0) {
        float w[10];
#pragma unroll
        for (int t = 0; t < 9; t++) w[t] = lw[(o * 64 + i) * 9 + t];
        w[9] = ((red[0][o] + red[1][o]) + (red[2][o] + red[3][o]));  // Sn tap

        const int ii = i & 7;
        const int slotbase = (ii & 3) * 2 + (ii >> 2);
        const int wbase = o * 320 + (i >> 3) * 40 + slotbase;
#pragma unroll
        for (int j = 0; j < 5; j++)
            g_A[wbase + 8 * j] = h2pack(w[2 * j], w[2 * j + 1]);

        if (i == 0) {
            float c = 0.f;
            for (int q = 0; q < 4; q++) {
                const float* wb = w2bw + q * 4096 + o * 64;
                const float* ab = w2ab + q * 64;
                float hh = 0.f;
#pragma unroll 8
                for (int mm = 0; mm < 64; mm++) hh = fmaf(wb[mm], ab[mm], hh);
                c += hh + w2bb[q * 64 + o];
            }
            g_bias[o] = lb[o] + c;
        }
    }
}

// Build fp16 features for 8 channels (4 channel-pairs) from the half2 X tile.
// Xh layout: word ((c2*3 + r)*256 + px) = half2(x[ch=c2], x[ch=c2+4]) at px.
// mk2[9]: half2 zero-pad mask multipliers (1.0/0.0; conv taps only, Sn circular).
// B word slots: (c2*2 + h) + 8*j  (h=0 lo-channel, h=1 hi-channel).
__device__ __forceinline__ void build_B(u32* Bs, const u32* Xh, int cx,
                                        int xm1, int xp1, const u32* mk2) {
    u32* bp = Bs + cx * BST;
#pragma unroll
    for (int c2 = 0; c2 < 4; c2++) {
        const u32* base = Xh + c2 * 768;
        u32 m[9];
#pragma unroll
        for (int r = 0; r < 3; r++) {
            m[r * 3 + 0] = base[r * 256 + xm1];
            m[r * 3 + 1] = base[r * 256 + cx];
            m[r * 3 + 2] = base[r * 256 + xp1];
        }
        // Sn from raw (circular) values, both channels
        float vl[9], vh[9];
#pragma unroll
        for (int t = 0; t < 9; t++) {
            float2 vf = __half22float2(*reinterpret_cast<const __half2*>(&m[t]));
            vl[t] = vf.x; vh[t] = vf.y;
        }
        float sl = ((vl[0] + vl[1]) + (vl[2] + vl[3])) +
                   ((vl[4] + vl[5]) + (vl[6] + vl[7])) + vl[8];
        float sh = ((vh[0] + vh[1]) + (vh[2] + vh[3])) +
                   ((vh[4] + vh[5]) + (vh[6] + vh[7])) + vh[8];
        float s2l = vl[0] * vl[0], s2h = vh[0] * vh[0];
#pragma unroll
        for (int t = 1; t < 9; t++) {
            s2l = fmaf(vl[t], vl[t], s2l);
            s2h = fmaf(vh[t], vh[t], s2h);
        }
        const float Snl = fmaf(sl, sl, s2l) * (1.0f / 90.0f);
        const float Snh = fmaf(sh, sh, s2h) * (1.0f / 90.0f);
        const u32 sn2 = h2pack(Snl, Snh);

        u32 mm[9];
#pragma unroll
        for (int t = 0; t < 9; t++) mm[t] = hmul2(m[t], mk2[t]);

#pragma unroll
        for (int j = 0; j < 4; j++) {
            u32 wl = prmt(mm[2 * j], mm[2 * j + 1], 0x5410u);  // lo-channel taps
            u32 wh = prmt(mm[2 * j], mm[2 * j + 1], 0x7632u);  // hi-channel taps
            *(uint2*)(bp + c2 * 2 + 8 * j) = make_uint2(wl, wh);
        }
        u32 wl4 = prmt(mm[8], sn2, 0x5410u);
        u32 wh4 = prmt(mm[8], sn2, 0x7632u);
        *(uint2*)(bp + c2 * 2 + 32) = make_uint2(wl4, wh4);
    }
}

// 2048 CTAs (blockIdx.x = b*256 + y), 256 threads (8 warps), 2 CTAs/SM.
// Warp w owns output tile oc[0..63] x px[w*32..w*32+31]; fp16 m16n8k16.
// Smem: A double (cp.async), B single, Xh double (half2 pairs, LDG-staged).
// Body: sync; cp.async A(i+1); LDG X(i+1); MMA(i); STS Xh(i+1); wait; sync; build(i+1).
__global__ __launch_bounds__(256, 2)
void volterra_hmma(const float* __restrict__ x, float* __restrict__ out) {
    extern __shared__ u32 smem[];
    const u32 As_b = smem_u32(smem);                 // + buf*A_WORDS*4
    u32* Bs = smem + 2 * A_WORDS;
    u32* Xh0 = smem + 2 * A_WORDS + B_WORDS;
    u32* Xh1 = Xh0 + XH_WORDS;
    const u32 Bs_b = As_b + 2 * A_WORDS * 4;

    const int tid = (int)threadIdx.x;
    const int w = tid >> 5;
    const int lane = tid & 31;
    const int b = (int)blockIdx.x >> 8;
    const int y = (int)blockIdx.x & 255;
    const int cx = tid;
    const int xm1 = (cx - 1) & 255, xp1 = (cx + 1) & 255;

    const float* xb = x + ((size_t)b << 22);

    // half2 zero-pad mask multipliers (per-thread constants)
    const float cm0 = (cx != 0) ? 1.f : 0.f;
    const float cm2 = (cx != 255) ? 1.f : 0.f;
    const float rm0 = (y != 0) ? 1.f : 0.f;
    const float rm2 = (y != 255) ? 1.f : 0.f;
    const float mkf[9] = { rm0 * cm0, rm0, rm0 * cm2,
                           cm0,       1.f, cm2,
                           rm2 * cm0, rm2, rm2 * cm2 };
    u32 mk2[9];
#pragma unroll
    for (int t = 0; t < 9; t++) mk2[t] = h2pack(mkf[t], mkf[t]);

    // ldmatrix lane-role
    const int lrow = lane & 15;
    const int lcol = (lane >> 4) * 4;

    float acc[4][4][4];
#pragma unroll
    for (int m = 0; m < 4; m++)
#pragma unroll
        for (int n = 0; n < 4; n++)
#pragma unroll
            for (int r = 0; r < 4; r++) acc[m][n][r] = 0.f;

    // A-stage roles: 640 quads over 256 threads, 3 passes
    int aq_off[3], aq_src[3];
#pragma unroll
    for (int p = 0; p < 3; p++) {
        int idx = tid + p * 256;
        int oc = idx / 10, j = idx - oc * 10;
        aq_off[p] = (oc * AST + j * 4) << 2;
        aq_src[p] = oc * 320 + j * 4;       // + iter*40
    }
    // X-stage roles: 1536 u64 units over 256 threads, 6 passes
    int xoff[6], xdstw[6];
    {
        const int rowoff[3] = { ((y - 1) & 255) << 8, y << 8, ((y + 1) & 255) << 8 };
#pragma unroll
        for (int u = 0; u < 6; u++) {
            int q = tid + u * 256;
            int c2 = q / 384, rem = q - c2 * 384;
            int r = rem >> 7, pxh = rem & 127;
            xoff[u] = (c2 << 16) + rowoff[r] + (pxh << 1);     // ch-lo f32 offset
            xdstw[u] = c2 * 768 + (r << 8) + (pxh << 1);       // Xh word offset
        }
    }

    // prologue: stage A(0) (cp.async) + X(0) (LDG+cvt), then build B(0)
#pragma unroll
    for (int p = 0; p < 3; p++) {
        if (tid + p * 256 < 640)
            cp_async16(As_b + (u32)aq_off[p], g_A + aq_src[p]);
    }
    asm volatile("cp.async.commit_group;" ::: "memory");
    {
        float2 lo[6], hi[6];
#pragma unroll
        for (int u = 0; u < 6; u++) {
            lo[u] = *(const float2*)(xb + xoff[u]);
            hi[u] = *(const float2*)(xb + xoff[u] + (4 << 16));
        }
#pragma unroll
        for (int u = 0; u < 6; u++) {
            *(uint2*)(Xh0 + xdstw[u]) =
                make_uint2(h2pack(lo[u].x, hi[u].x), h2pack(lo[u].y, hi[u].y));
        }
    }
    asm volatile("cp.async.wait_group 0;" ::: "memory");
    __syncthreads();
    build_B(Bs, Xh0, cx, xm1, xp1, mk2);

#pragma unroll 1
    for (int iter = 0; iter < 8; iter++) {
        const int buf = iter & 1;
        const int nbuf = buf ^ 1;
        u32* XhN = (nbuf == 0) ? Xh0 : Xh1;

        __syncthreads();  // build(iter) STS visible everywhere

        // stage A(iter+1) via cp.async + issue X(iter+1) LDGs (overlap MMA)
        float2 lo[6], hi[6];
        if (iter < 7) {
            const u32* gAn = g_A + (iter + 1) * 40;
            const u32 abase = As_b + (u32)(nbuf * A_WORDS * 4);
#pragma unroll
            for (int p = 0; p < 3; p++) {
                if (tid + p * 256 < 640)
                    cp_async16(abase + (u32)aq_off[p], gAn + aq_src[p]);
            }
            const float* xn = xb + ((size_t)((iter + 1) * 8) << 16);
#pragma unroll
            for (int u = 0; u < 6; u++) {
                lo[u] = *(const float2*)(xn + xoff[u]);
                hi[u] = *(const float2*)(xn + xoff[u] + (4 << 16));
            }
        }
        asm volatile("cp.async.commit_group;" ::: "memory");

        // ---- MMA(iter): 5 k16-steps, fragments via ldmatrix.x4 ----
        const u32 Ab = As_b + (u32)(buf * A_WORDS * 4);
#pragma unroll
        for (int k5 = 0; k5 < 5; k5++) {
            u32 a[4][4];
#pragma unroll
            for (int m = 0; m < 4; m++)
                ldmx4(a[m], Ab + (u32)(((m * 16 + lrow) * AST + k5 * 8 + lcol) << 2));
#pragma unroll
            for (int np = 0; np < 2; np++) {
                u32 bb[4];
                ldmx4(bb, Bs_b + (u32)(((w * 32 + np * 16 + lrow) * BST + k5 * 8 + lcol) << 2));
#pragma unroll
                for (int m = 0; m < 4; m++) {
                    mma_f16(acc[m][2 * np + 0], a[m], bb[0], bb[2]);
                    mma_f16(acc[m][2 * np + 1], a[m], bb[1], bb[3]);
                }
            }
        }

        if (iter < 7) {
            // convert + store X(iter+1) (LDG data arrived under the MMAs)
#pragma unroll
            for (int u = 0; u < 6; u++) {
                *(uint2*)(XhN + xdstw[u]) =
                    make_uint2(h2pack(lo[u].x, hi[u].x), h2pack(lo[u].y, hi[u].y));
            }
            asm volatile("cp.async.wait_group 0;" ::: "memory");
            __syncthreads();  // MMA reads of B done; A(iter+1)+Xh(iter+1) landed
            build_B(Bs, XhN, cx, xm1, xp1, mk2);  // write B(iter+1)
        }
    }

    // ---- epilogue: bias + float2 stores (fragment-native layout, verified) ----
    const int r_ = lane >> 2, cc_ = lane & 3;
#pragma unroll
    for (int m = 0; m < 4; m++) {
        const int oc0 = m * 16 + r_;
        const int oc1 = oc0 + 8;
        const float bo0 = g_bias[oc0];
        const float bo1 = g_bias[oc1];
        float* p0 = out + (((size_t)(b * 64 + oc0)) << 16) + (y << 8) + w * 32 + cc_ * 2;
        float* p1 = out + (((size_t)(b * 64 + oc1)) << 16) + (y << 8) + w * 32 + cc_ * 2;
#pragma unroll
        for (int n = 0; n < 4; n++) {
            float2 s0 = make_float2(acc[m][n][0] + bo0, acc[m][n][1] + bo0);
            float2 s1 = make_float2(acc[m][n][2] + bo1, acc[m][n][3] + bo1);
            *(float2*)(p0 + n * 8) = s0;
            *(float2*)(p1 + n * 8) = s1;
        }
    }
}

}  // namespace

extern "C" void kernel_launch(void* const* d_in, const int* in_sizes, int n_in,
                              void* d_out, int out_size) {
    (void)in_sizes; (void)n_in; (void)out_size;
    const float* x    = (const float*)d_in[0];
    const float* lw   = (const float*)d_in[1];
    const float* lb   = (const float*)d_in[2];
    const float* w2aw = (const float*)d_in[3];
    const float* w2ab = (const float*)d_in[4];
    const float* w2bw = (const float*)d_in[5];
    const float* w2bb = (const float*)d_in[6];
    float* out = (float*)d_out;

    static int attr_set = 0;
    if (!attr_set) {
        cudaFuncSetAttribute(volterra_hmma,
                             cudaFuncAttributeMaxDynamicSharedMemorySize, SMEM_TOTAL);
        attr_set = 1;
    }
    precompute_kernel<<<64, 256>>>(lw, lb, w2aw, w2ab, w2bw, w2bb);
    volterra_hmma<<<2048, 256, SMEM_TOTAL>>>(x, out);
}